// round 2
// baseline (speedup 1.0000x reference)
#include <cuda_runtime.h>
#include <cstdint>
#include <cstddef>

#define BATCH 256
#define SEQT  365
#define HID   256
#define INSZ  32
#define G4    1024          // 4*HID
#define NB    128           // persistent blocks
#define NT    256           // threads per block (= BATCH)

// ---------------- scratch (static device allocations; no cudaMalloc) ----------
__device__ float g_xw[(size_t)SEQT * G4 * BATCH];   // [t][gatecol][b], bias folded in (382 MB)
__device__ float g_h[2][HID * BATCH];               // double-buffered hidden state, [j][b]
__device__ unsigned g_bar_count;                    // zero-init, returns to 0 after each barrier
__device__ unsigned g_bar_gen;

// ---------------- packed f32x2 helpers (PTX-only; ptxas won't auto-fuse) ------
__device__ __forceinline__ unsigned long long pack2(float lo, float hi) {
    unsigned long long r;
    asm("mov.b64 %0, {%1, %2};" : "=l"(r) : "f"(lo), "f"(hi));
    return r;
}
__device__ __forceinline__ void unpack2(unsigned long long v, float& lo, float& hi) {
    asm("mov.b64 {%0, %1}, %2;" : "=f"(lo), "=f"(hi) : "l"(v));
}
__device__ __forceinline__ unsigned long long fma2(unsigned long long a,
                                                   unsigned long long b,
                                                   unsigned long long c) {
    unsigned long long d;
    asm("fma.rn.f32x2 %0, %1, %2, %3;" : "=l"(d) : "l"(a), "l"(b), "l"(c));
    return d;
}

__device__ __forceinline__ float sigf(float x) {
    return 1.0f / (1.0f + __expf(-x));
}

// ---------------- grid barrier (all NB CTAs co-resident by construction) ------
__device__ __forceinline__ void grid_barrier() {
    __syncthreads();
    if (threadIdx.x == 0) {
        volatile unsigned* genp = &g_bar_gen;
        unsigned gen = *genp;
        __threadfence();                       // make this CTA's h writes L2-visible
        if (atomicAdd(&g_bar_count, 1u) == NB - 1u) {
            g_bar_count = 0;
            __threadfence();
            *genp = gen + 1u;                  // release
        } else {
            while (*genp == gen) { }           // spin (L2, bypasses L1 via volatile)
        }
    }
    __syncthreads();
}

// ============================================================================
// Kernel A: xw[t][j][b] = sum_k x[b][t][k] * w_ih[k][j] + bias[j]
// grid (SEQT, 8): each block does one t and a 128-wide j tile.
// ============================================================================
__global__ void __launch_bounds__(NT) xw_kernel(const float* __restrict__ x,
                                                const float* __restrict__ w_ih,
                                                const float* __restrict__ bias) {
    __shared__ float ws[INSZ * 128];      // [k][j_local], 16 KB
    const int t  = blockIdx.x;
    const int j0 = blockIdx.y * 128;
    const int tid = threadIdx.x;

    for (int i = tid; i < INSZ * 128; i += NT) {
        int k = i >> 7, j = i & 127;
        ws[i] = w_ih[(size_t)k * G4 + j0 + j];
    }
    __syncthreads();

    const int b = tid;
    float xr[INSZ];
    const float4* xp = (const float4*)(x + ((size_t)b * SEQT + t) * INSZ);
#pragma unroll
    for (int q = 0; q < INSZ / 4; q++) {
        float4 v = xp[q];
        xr[4 * q + 0] = v.x; xr[4 * q + 1] = v.y;
        xr[4 * q + 2] = v.z; xr[4 * q + 3] = v.w;
    }

    for (int jq = 0; jq < 32; jq++) {             // 4 output columns per iter
        float4 bq = *(const float4*)(bias + j0 + jq * 4);
        unsigned long long a0 = pack2(bq.x, bq.y);
        unsigned long long a1 = pack2(bq.z, bq.w);
#pragma unroll
        for (int k = 0; k < INSZ; k++) {
            ulonglong2 w = *(const ulonglong2*)(ws + k * 128 + jq * 4);  // broadcast LDS.128
            unsigned long long xk = pack2(xr[k], xr[k]);
            a0 = fma2(xk, w.x, a0);
            a1 = fma2(xk, w.y, a1);
        }
        float f0, f1, f2, f3;
        unpack2(a0, f0, f1);
        unpack2(a1, f2, f3);
        size_t base = ((size_t)t * G4 + j0 + jq * 4) * BATCH + b;
        g_xw[base]             = f0;
        g_xw[base + BATCH]     = f1;
        g_xw[base + 2 * BATCH] = f2;
        g_xw[base + 3 * BATCH] = f3;
    }
}

// ============================================================================
// Kernel B: persistent recurrent LSTM. Block bid owns hidden units {2bid, 2bid+1}
// (8 gate columns of w_hh, resident in SMEM). Thread = batch row. c stays in regs.
// Gate order per reference: f | i | o | g (chunks of 256).
// ============================================================================
__global__ void __launch_bounds__(NT) lstm_kernel(const float* __restrict__ w_hh,
                                                  const float* __restrict__ fc_w,
                                                  const float* __restrict__ fc_b,
                                                  float* __restrict__ out) {
    __shared__ float ws[HID * 8];        // [k][c], c = gate*2 + unit (8 KB)
    __shared__ float red[NT];

    const int bid = blockIdx.x;
    const int tid = threadIdx.x;
    const int u0  = bid * 2;

    for (int i = tid; i < HID * 8; i += NT) {
        int k = i >> 3, c = i & 7;
        ws[i] = w_hh[(size_t)k * G4 + (c >> 1) * HID + u0 + (c & 1)];
    }
    __syncthreads();

    const int b = tid;
    float c0 = 0.0f, c1 = 0.0f;

    float* outO = out;                                  // [BATCH]
    float* outH = out + BATCH;                          // [BATCH][SEQT][HID]
    float* outC = outH + (size_t)BATCH * SEQT * HID;    // [BATCH][SEQT][HID]

    for (int t = 0; t < SEQT; t++) {
        const size_t xb = (size_t)t * G4 * BATCH + b;
        unsigned long long aF = pack2(g_xw[xb + (size_t)(0 * HID + u0) * BATCH],
                                      g_xw[xb + (size_t)(0 * HID + u0 + 1) * BATCH]);
        unsigned long long aI = pack2(g_xw[xb + (size_t)(1 * HID + u0) * BATCH],
                                      g_xw[xb + (size_t)(1 * HID + u0 + 1) * BATCH]);
        unsigned long long aO = pack2(g_xw[xb + (size_t)(2 * HID + u0) * BATCH],
                                      g_xw[xb + (size_t)(2 * HID + u0 + 1) * BATCH]);
        unsigned long long aG = pack2(g_xw[xb + (size_t)(3 * HID + u0) * BATCH],
                                      g_xw[xb + (size_t)(3 * HID + u0 + 1) * BATCH]);

        if (t > 0) {
            const float* hp = g_h[t & 1];
#pragma unroll 8
            for (int k = 0; k < HID; k++) {
                float hk = __ldcg(hp + (size_t)k * BATCH + b);   // L2 only: buffer is reused
                unsigned long long h2 = pack2(hk, hk);
                ulonglong2 wA = *(const ulonglong2*)(ws + k * 8);       // (f0,f1),(i0,i1)
                ulonglong2 wB = *(const ulonglong2*)(ws + k * 8 + 4);   // (o0,o1),(g0,g1)
                aF = fma2(h2, wA.x, aF);
                aI = fma2(h2, wA.y, aI);
                aO = fma2(h2, wB.x, aO);
                aG = fma2(h2, wB.y, aG);
            }
        }

        float f0, f1, i0, i1, o0, o1, gg0, gg1;
        unpack2(aF, f0, f1);
        unpack2(aI, i0, i1);
        unpack2(aO, o0, o1);
        unpack2(aG, gg0, gg1);

        c0 = sigf(f0) * c0 + sigf(i0) * tanhf(gg0);
        c1 = sigf(f1) * c1 + sigf(i1) * tanhf(gg1);
        float h0 = sigf(o0) * tanhf(c0);
        float h1 = sigf(o1) * tanhf(c1);

        float* hw = g_h[(t + 1) & 1];
        hw[(size_t)u0 * BATCH + b]       = h0;
        hw[(size_t)(u0 + 1) * BATCH + b] = h1;

        size_t ob = ((size_t)b * SEQT + t) * HID + u0;
        *(float2*)(outH + ob) = make_float2(h0, h1);
        *(float2*)(outC + ob) = make_float2(c0, c1);

        grid_barrier();
    }

    // ---- final FC: out[b] = h_last[b,:] . fc_w + fc_b; block handles 2 rows ----
    const float* hl = g_h[SEQT & 1];     // buffer written at t = SEQT-1
    float fw = fc_w[tid];
    float fb = fc_b[0];
    for (int bb = 0; bb < 2; bb++) {
        int bo = bid * 2 + bb;
        red[tid] = __ldcg(hl + (size_t)tid * BATCH + bo) * fw;
        __syncthreads();
        for (int s = NT / 2; s > 0; s >>= 1) {
            if (tid < s) red[tid] += red[tid + s];
            __syncthreads();
        }
        if (tid == 0) outO[bo] = red[0] + fb;
        __syncthreads();
    }
}

// ============================================================================
extern "C" void kernel_launch(void* const* d_in, const int* in_sizes, int n_in,
                              void* d_out, int out_size) {
    const float* x    = (const float*)d_in[0];  // (256, 365, 32)
    const float* w_ih = (const float*)d_in[1];  // (32, 1024)
    const float* w_hh = (const float*)d_in[2];  // (256, 1024)
    const float* bias = (const float*)d_in[3];  // (1024,)
    const float* fc_w = (const float*)d_in[4];  // (256, 1)
    const float* fc_b = (const float*)d_in[5];  // (1,)
    float* out = (float*)d_out;

    dim3 gA(SEQT, 8);
    xw_kernel<<<gA, NT>>>(x, w_ih, bias);
    lstm_kernel<<<NB, NT>>>(w_hh, fc_w, fc_b, out);
}

// round 3
// speedup vs baseline: 1.6441x; 1.6441x over previous
#include <cuda_runtime.h>
#include <cstdint>
#include <cstddef>

#define BATCH 256
#define SEQT  365
#define HID   256
#define INSZ  32
#define G4    1024          // 4*HID
#define NB    128           // persistent blocks
#define NT    256           // threads per block (= BATCH)
#define NPAIR (HID / 2)     // 128 unit pairs

typedef unsigned long long ull;

// ---------------- scratch (static device allocations; no cudaMalloc) ----------
// xw packed per unit-pair: [t][pair][2][b] float4
//   slot 0 = (f0,f1,i0,i1), slot 1 = (o0,o1,g0,g1), bias folded in. 382 MB.
__device__ float4 g_xw4[(size_t)SEQT * NPAIR * 2 * BATCH];
// hidden state, double buffered, packed 4 units per float4: [buf][k4][b]
__device__ float4 g_h4[2][(HID / 4) * BATCH];
__device__ unsigned g_bar_count;
__device__ unsigned g_bar_gen;

// ---------------- packed f32x2 helpers (PTX-only; ptxas won't auto-fuse) ------
__device__ __forceinline__ ull pack2(float lo, float hi) {
    ull r;
    asm("mov.b64 %0, {%1, %2};" : "=l"(r) : "f"(lo), "f"(hi));
    return r;
}
__device__ __forceinline__ void unpack2(ull v, float& lo, float& hi) {
    asm("mov.b64 {%0, %1}, %2;" : "=f"(lo), "=f"(hi) : "l"(v));
}
__device__ __forceinline__ ull fma2(ull a, ull b, ull c) {
    ull d;
    asm("fma.rn.f32x2 %0, %1, %2, %3;" : "=l"(d) : "l"(a), "l"(b), "l"(c));
    return d;
}
__device__ __forceinline__ float sigf(float x) { return 1.0f / (1.0f + __expf(-x)); }

// ---------------- grid barrier (all NB CTAs co-resident by construction) ------
__device__ __forceinline__ void grid_barrier() {
    __syncthreads();
    if (threadIdx.x == 0) {
        volatile unsigned* genp = &g_bar_gen;
        unsigned gen = *genp;
        __threadfence();                       // make h writes L2-visible
        if (atomicAdd(&g_bar_count, 1u) == NB - 1u) {
            g_bar_count = 0;
            __threadfence();
            *genp = gen + 1u;                  // release
        } else {
            while (*genp == gen) { }           // spin in L2
        }
    }
    __syncthreads();
}

// ============================================================================
// Kernel A: xw. grid (SEQT, 8); block = one t, a 32-unit tile (16 pairs).
// Output layout matches lstm reader: g_xw4[t][pair][slot][b].
// ============================================================================
__global__ void __launch_bounds__(NT) xw_kernel(const float* __restrict__ x,
                                                const float* __restrict__ w_ih,
                                                const float* __restrict__ bias) {
    __shared__ float ws[INSZ][16][8];     // [k][pair_local][c], c=(f0,f1,i0,i1,o0,o1,g0,g1)
    const int t   = blockIdx.x;
    const int u00 = blockIdx.y * 32;      // first unit of tile
    const int tid = threadIdx.x;

    for (int i = tid; i < INSZ * 128; i += NT) {
        int k = i >> 7, r = i & 127, p = r >> 3, c = r & 7;
        int unit = u00 + 2 * p + (c & 1);
        ws[k][p][c] = w_ih[(size_t)k * G4 + (c >> 1) * HID + unit];
    }
    __syncthreads();

    const int b = tid;
    ull xk2[INSZ];
    const float4* xp = (const float4*)(x + ((size_t)b * SEQT + t) * INSZ);
#pragma unroll
    for (int q = 0; q < INSZ / 4; q++) {
        float4 v = xp[q];
        xk2[4 * q + 0] = pack2(v.x, v.x);
        xk2[4 * q + 1] = pack2(v.y, v.y);
        xk2[4 * q + 2] = pack2(v.z, v.z);
        xk2[4 * q + 3] = pack2(v.w, v.w);
    }

    for (int p = 0; p < 16; p++) {
        int u = u00 + 2 * p;
        ull aF = pack2(bias[u],           bias[u + 1]);
        ull aI = pack2(bias[HID + u],     bias[HID + u + 1]);
        ull aO = pack2(bias[2 * HID + u], bias[2 * HID + u + 1]);
        ull aG = pack2(bias[3 * HID + u], bias[3 * HID + u + 1]);
#pragma unroll
        for (int k = 0; k < INSZ; k++) {
            ulonglong2 wA = *(const ulonglong2*)(&ws[k][p][0]);
            ulonglong2 wB = *(const ulonglong2*)(&ws[k][p][4]);
            aF = fma2(xk2[k], wA.x, aF);
            aI = fma2(xk2[k], wA.y, aI);
            aO = fma2(xk2[k], wB.x, aO);
            aG = fma2(xk2[k], wB.y, aG);
        }
        float f0, f1, i0, i1, o0, o1, g0, g1;
        unpack2(aF, f0, f1); unpack2(aI, i0, i1);
        unpack2(aO, o0, o1); unpack2(aG, g0, g1);
        size_t base = (((size_t)t * NPAIR + (u00 / 2 + p)) * 2) * BATCH + b;
        __stcs(&g_xw4[base],         make_float4(f0, f1, i0, i1));
        __stcs(&g_xw4[base + BATCH], make_float4(o0, o1, g0, g1));
    }
}

// ============================================================================
// Kernel B: persistent recurrent LSTM. CTA owns units u0=2*bid, u0+1; thread=batch.
// h loads pipelined in register chunks of 8 float4 (32 k) to hide L2 latency.
// ============================================================================
__global__ void __launch_bounds__(NT, 1) lstm_kernel(const float* __restrict__ w_hh,
                                                     const float* __restrict__ fc_w,
                                                     const float* __restrict__ fc_b,
                                                     float* __restrict__ out) {
    __shared__ float ws[HID][8];         // [k][c], 8 KB
    __shared__ float red[NT];

    const int bid = blockIdx.x;
    const int tid = threadIdx.x;
    const int u0  = bid * 2;
    const int b   = tid;

    for (int i = tid; i < HID * 8; i += NT) {
        int k = i >> 3, c = i & 7;
        ws[k][c] = w_hh[(size_t)k * G4 + (c >> 1) * HID + u0 + (c & 1)];
    }
    __syncthreads();

    float c0 = 0.0f, c1 = 0.0f;

    float* outO = out;
    float* outH = out + BATCH;
    float* outC = outH + (size_t)BATCH * SEQT * HID;

    // xw prefetch for t = 0
    const size_t xw_stride_t = (size_t)NPAIR * 2 * BATCH;
    const float4* xwp = g_xw4 + (size_t)bid * 2 * BATCH + b;   // pair = bid
    float4 xA = __ldcs(xwp);
    float4 xB = __ldcs(xwp + BATCH);

    for (int t = 0; t < SEQT; t++) {
        ull aF = pack2(xA.x, xA.y);
        ull aI = pack2(xA.z, xA.w);
        ull aO = pack2(xB.x, xB.y);
        ull aG = pack2(xB.z, xB.w);

        // prefetch next t's xw (DRAM latency hidden under the k-loop)
        if (t + 1 < SEQT) {
            const float4* nx = xwp + (size_t)(t + 1) * xw_stride_t;
            xA = __ldcs(nx);
            xB = __ldcs(nx + BATCH);
        }

        if (t > 0) {
            const float4* hp = (const float4*)g_h4[t & 1];
            float4 hb[2][8];
#pragma unroll
            for (int i = 0; i < 8; i++)
                hb[0][i] = __ldcg(hp + i * BATCH + b);
#pragma unroll
            for (int c = 0; c < 8; c++) {
                if (c < 7) {
#pragma unroll
                    for (int i = 0; i < 8; i++)
                        hb[(c + 1) & 1][i] = __ldcg(hp + ((c + 1) * 8 + i) * BATCH + b);
                }
#pragma unroll
                for (int i = 0; i < 8; i++) {
                    float4 v = hb[c & 1][i];
                    const float* wr = &ws[(c * 8 + i) * 4][0];
#pragma unroll
                    for (int s = 0; s < 4; s++) {
                        float hv = (s == 0) ? v.x : (s == 1) ? v.y : (s == 2) ? v.z : v.w;
                        ull h2 = pack2(hv, hv);
                        ulonglong2 wA = *(const ulonglong2*)(wr + 8 * s);
                        ulonglong2 wB = *(const ulonglong2*)(wr + 8 * s + 4);
                        aF = fma2(h2, wA.x, aF);
                        aI = fma2(h2, wA.y, aI);
                        aO = fma2(h2, wB.x, aO);
                        aG = fma2(h2, wB.y, aG);
                    }
                }
            }
        }

        float f0, f1, i0, i1, o0, o1, gg0, gg1;
        unpack2(aF, f0, f1); unpack2(aI, i0, i1);
        unpack2(aO, o0, o1); unpack2(aG, gg0, gg1);

        c0 = sigf(f0) * c0 + sigf(i0) * tanhf(gg0);
        c1 = sigf(f1) * c1 + sigf(i1) * tanhf(gg1);
        float h0 = sigf(o0) * tanhf(c0);
        float h1 = sigf(o1) * tanhf(c1);

        // write packed h: g_h4[(t+1)&1][u0>>2][b], float2 at component (u0&3)
        {
            float* hw = (float*)&g_h4[(t + 1) & 1][(u0 >> 2) * BATCH + b];
            *(float2*)(hw + (u0 & 3)) = make_float2(h0, h1);
        }

        size_t ob = ((size_t)b * SEQT + t) * HID + u0;
        __stcs((float2*)(outH + ob), make_float2(h0, h1));
        __stcs((float2*)(outC + ob), make_float2(c0, c1));

        grid_barrier();
    }

    // ---- final FC: out[bo] = h_last[bo,:] . fc_w + fc_b ----
    const float* hl = (const float*)g_h4[SEQT & 1];
    float fw = fc_w[tid];
    float fb = fc_b[0];
    for (int bb = 0; bb < 2; bb++) {
        int bo = bid * 2 + bb;
        // h_last[k=tid][b=bo] lives at float4 index (tid>>2)*BATCH + bo, comp tid&3
        red[tid] = __ldcg(hl + ((tid >> 2) * BATCH + bo) * 4 + (tid & 3)) * fw;
        __syncthreads();
        for (int s = NT / 2; s > 0; s >>= 1) {
            if (tid < s) red[tid] += red[tid + s];
            __syncthreads();
        }
        if (tid == 0) outO[bo] = red[0] + fb;
        __syncthreads();
    }
}

// ============================================================================
extern "C" void kernel_launch(void* const* d_in, const int* in_sizes, int n_in,
                              void* d_out, int out_size) {
    const float* x    = (const float*)d_in[0];  // (256, 365, 32)
    const float* w_ih = (const float*)d_in[1];  // (32, 1024)
    const float* w_hh = (const float*)d_in[2];  // (256, 1024)
    const float* bias = (const float*)d_in[3];  // (1024,)
    const float* fc_w = (const float*)d_in[4];  // (256, 1)
    const float* fc_b = (const float*)d_in[5];  // (1,)
    float* out = (float*)d_out;

    dim3 gA(SEQT, 8);
    xw_kernel<<<gA, NT>>>(x, w_ih, bias);
    lstm_kernel<<<NB, NT>>>(w_hh, fc_w, fc_b, out);
}

// round 4
// speedup vs baseline: 1.6469x; 1.0017x over previous
#include <cuda_runtime.h>
#include <cstdint>
#include <cstddef>

#define BATCH 256
#define SEQT  365
#define HID   256
#define INSZ  32
#define G4    1024          // 4*HID
#define NB    128           // persistent blocks
#define NT    256           // threads per block (= BATCH)
#define NPAIR (HID / 2)     // 128 unit pairs

typedef unsigned long long ull;

// ---------------- scratch (static device allocations; no cudaMalloc) ----------
// xw packed per unit-pair: [t][pair][2][b] float4
//   slot 0 = (f0,f1,i0,i1), slot 1 = (o0,o1,g0,g1), bias folded in. 382 MB.
__device__ float4 g_xw4[(size_t)SEQT * NPAIR * 2 * BATCH];
// hidden state, double buffered, packed 4 units per float4: [buf][k4][b]
__device__ float4 g_h4[2][(HID / 4) * BATCH];
__device__ unsigned g_bar_count;
__device__ unsigned g_bar_gen;

// ---------------- packed f32x2 helpers (PTX-only; ptxas won't auto-fuse) ------
__device__ __forceinline__ ull pack2(float lo, float hi) {
    ull r;
    asm("mov.b64 %0, {%1, %2};" : "=l"(r) : "f"(lo), "f"(hi));
    return r;
}
__device__ __forceinline__ void unpack2(ull v, float& lo, float& hi) {
    asm("mov.b64 {%0, %1}, %2;" : "=f"(lo), "=f"(hi) : "l"(v));
}
__device__ __forceinline__ ull fma2(ull a, ull b, ull c) {
    ull d;
    asm("fma.rn.f32x2 %0, %1, %2, %3;" : "=l"(d) : "l"(a), "l"(b), "l"(c));
    return d;
}
__device__ __forceinline__ float sigf(float x) { return 1.0f / (1.0f + __expf(-x)); }

// ---------------- grid barrier (all NB CTAs co-resident by construction) ------
__device__ __forceinline__ void grid_barrier() {
    __syncthreads();
    if (threadIdx.x == 0) {
        volatile unsigned* genp = &g_bar_gen;
        unsigned gen = *genp;
        __threadfence();                       // make h writes L2-visible
        if (atomicAdd(&g_bar_count, 1u) == NB - 1u) {
            g_bar_count = 0;
            __threadfence();
            *genp = gen + 1u;                  // release
        } else {
            while (*genp == gen) { }           // spin in L2
        }
    }
    __syncthreads();
}

// ============================================================================
// Kernel A: xw. grid (SEQT, 8); block = one t, a 32-unit tile (16 pairs).
// Output layout matches lstm reader: g_xw4[t][pair][slot][b].
// ============================================================================
__global__ void __launch_bounds__(NT) xw_kernel(const float* __restrict__ x,
                                                const float* __restrict__ w_ih,
                                                const float* __restrict__ bias) {
    __shared__ float ws[INSZ][16][8];     // [k][pair_local][c], c=(f0,f1,i0,i1,o0,o1,g0,g1)
    const int t   = blockIdx.x;
    const int u00 = blockIdx.y * 32;      // first unit of tile
    const int tid = threadIdx.x;

    for (int i = tid; i < INSZ * 128; i += NT) {
        int k = i >> 7, r = i & 127, p = r >> 3, c = r & 7;
        int unit = u00 + 2 * p + (c & 1);
        ws[k][p][c] = w_ih[(size_t)k * G4 + (c >> 1) * HID + unit];
    }
    __syncthreads();

    const int b = tid;
    ull xk2[INSZ];
    const float4* xp = (const float4*)(x + ((size_t)b * SEQT + t) * INSZ);
#pragma unroll
    for (int q = 0; q < INSZ / 4; q++) {
        float4 v = xp[q];
        xk2[4 * q + 0] = pack2(v.x, v.x);
        xk2[4 * q + 1] = pack2(v.y, v.y);
        xk2[4 * q + 2] = pack2(v.z, v.z);
        xk2[4 * q + 3] = pack2(v.w, v.w);
    }

    for (int p = 0; p < 16; p++) {
        int u = u00 + 2 * p;
        ull aF = pack2(bias[u],           bias[u + 1]);
        ull aI = pack2(bias[HID + u],     bias[HID + u + 1]);
        ull aO = pack2(bias[2 * HID + u], bias[2 * HID + u + 1]);
        ull aG = pack2(bias[3 * HID + u], bias[3 * HID + u + 1]);
#pragma unroll
        for (int k = 0; k < INSZ; k++) {
            ulonglong2 wA = *(const ulonglong2*)(&ws[k][p][0]);
            ulonglong2 wB = *(const ulonglong2*)(&ws[k][p][4]);
            aF = fma2(xk2[k], wA.x, aF);
            aI = fma2(xk2[k], wA.y, aI);
            aO = fma2(xk2[k], wB.x, aO);
            aG = fma2(xk2[k], wB.y, aG);
        }
        float f0, f1, i0, i1, o0, o1, g0, g1;
        unpack2(aF, f0, f1); unpack2(aI, i0, i1);
        unpack2(aO, o0, o1); unpack2(aG, g0, g1);
        size_t base = (((size_t)t * NPAIR + (u00 / 2 + p)) * 2) * BATCH + b;
        __stcs(&g_xw4[base],         make_float4(f0, f1, i0, i1));
        __stcs(&g_xw4[base + BATCH], make_float4(o0, o1, g0, g1));
    }
}

// ============================================================================
// Kernel B: persistent recurrent LSTM. CTA owns units u0=2*bid, u0+1; thread=batch.
// h loads pipelined in register chunks of 8 float4 (32 k) to hide L2 latency.
// ============================================================================
__global__ void __launch_bounds__(NT, 1) lstm_kernel(const float* __restrict__ w_hh,
                                                     const float* __restrict__ fc_w,
                                                     const float* __restrict__ fc_b,
                                                     float* __restrict__ out) {
    __shared__ float ws[HID][8];         // [k][c], 8 KB
    __shared__ float red[NT];

    const int bid = blockIdx.x;
    const int tid = threadIdx.x;
    const int u0  = bid * 2;
    const int b   = tid;

    for (int i = tid; i < HID * 8; i += NT) {
        int k = i >> 3, c = i & 7;
        ws[k][c] = w_hh[(size_t)k * G4 + (c >> 1) * HID + u0 + (c & 1)];
    }
    __syncthreads();

    float c0 = 0.0f, c1 = 0.0f;

    float* outO = out;
    float* outH = out + BATCH;
    float* outC = outH + (size_t)BATCH * SEQT * HID;

    // xw prefetch for t = 0
    const size_t xw_stride_t = (size_t)NPAIR * 2 * BATCH;
    const float4* xwp = g_xw4 + (size_t)bid * 2 * BATCH + b;   // pair = bid
    float4 xA = __ldcs(xwp);
    float4 xB = __ldcs(xwp + BATCH);

    for (int t = 0; t < SEQT; t++) {
        ull aF = pack2(xA.x, xA.y);
        ull aI = pack2(xA.z, xA.w);
        ull aO = pack2(xB.x, xB.y);
        ull aG = pack2(xB.z, xB.w);

        // prefetch next t's xw (DRAM latency hidden under the k-loop)
        if (t + 1 < SEQT) {
            const float4* nx = xwp + (size_t)(t + 1) * xw_stride_t;
            xA = __ldcs(nx);
            xB = __ldcs(nx + BATCH);
        }

        if (t > 0) {
            const float4* hp = (const float4*)g_h4[t & 1];
            float4 hb[2][8];
#pragma unroll
            for (int i = 0; i < 8; i++)
                hb[0][i] = __ldcg(hp + i * BATCH + b);
#pragma unroll
            for (int c = 0; c < 8; c++) {
                if (c < 7) {
#pragma unroll
                    for (int i = 0; i < 8; i++)
                        hb[(c + 1) & 1][i] = __ldcg(hp + ((c + 1) * 8 + i) * BATCH + b);
                }
#pragma unroll
                for (int i = 0; i < 8; i++) {
                    float4 v = hb[c & 1][i];
                    const float* wr = &ws[(c * 8 + i) * 4][0];
#pragma unroll
                    for (int s = 0; s < 4; s++) {
                        float hv = (s == 0) ? v.x : (s == 1) ? v.y : (s == 2) ? v.z : v.w;
                        ull h2 = pack2(hv, hv);
                        ulonglong2 wA = *(const ulonglong2*)(wr + 8 * s);
                        ulonglong2 wB = *(const ulonglong2*)(wr + 8 * s + 4);
                        aF = fma2(h2, wA.x, aF);
                        aI = fma2(h2, wA.y, aI);
                        aO = fma2(h2, wB.x, aO);
                        aG = fma2(h2, wB.y, aG);
                    }
                }
            }
        }

        float f0, f1, i0, i1, o0, o1, gg0, gg1;
        unpack2(aF, f0, f1); unpack2(aI, i0, i1);
        unpack2(aO, o0, o1); unpack2(aG, gg0, gg1);

        c0 = sigf(f0) * c0 + sigf(i0) * tanhf(gg0);
        c1 = sigf(f1) * c1 + sigf(i1) * tanhf(gg1);
        float h0 = sigf(o0) * tanhf(c0);
        float h1 = sigf(o1) * tanhf(c1);

        // write packed h: g_h4[(t+1)&1][u0>>2][b], float2 at component (u0&3)
        {
            float* hw = (float*)&g_h4[(t + 1) & 1][(u0 >> 2) * BATCH + b];
            *(float2*)(hw + (u0 & 3)) = make_float2(h0, h1);
        }

        size_t ob = ((size_t)b * SEQT + t) * HID + u0;
        __stcs((float2*)(outH + ob), make_float2(h0, h1));
        __stcs((float2*)(outC + ob), make_float2(c0, c1));

        grid_barrier();
    }

    // ---- final FC: out[bo] = h_last[bo,:] . fc_w + fc_b ----
    const float* hl = (const float*)g_h4[SEQT & 1];
    float fw = fc_w[tid];
    float fb = fc_b[0];
    for (int bb = 0; bb < 2; bb++) {
        int bo = bid * 2 + bb;
        // h_last[k=tid][b=bo] lives at float4 index (tid>>2)*BATCH + bo, comp tid&3
        red[tid] = __ldcg(hl + ((tid >> 2) * BATCH + bo) * 4 + (tid & 3)) * fw;
        __syncthreads();
        for (int s = NT / 2; s > 0; s >>= 1) {
            if (tid < s) red[tid] += red[tid + s];
            __syncthreads();
        }
        if (tid == 0) outO[bo] = red[0] + fb;
        __syncthreads();
    }
}

// ============================================================================
extern "C" void kernel_launch(void* const* d_in, const int* in_sizes, int n_in,
                              void* d_out, int out_size) {
    const float* x    = (const float*)d_in[0];  // (256, 365, 32)
    const float* w_ih = (const float*)d_in[1];  // (32, 1024)
    const float* w_hh = (const float*)d_in[2];  // (256, 1024)
    const float* bias = (const float*)d_in[3];  // (1024,)
    const float* fc_w = (const float*)d_in[4];  // (256, 1)
    const float* fc_b = (const float*)d_in[5];  // (1,)
    float* out = (float*)d_out;

    dim3 gA(SEQT, 8);
    xw_kernel<<<gA, NT>>>(x, w_ih, bias);
    lstm_kernel<<<NB, NT>>>(w_hh, fc_w, fc_b, out);
}